// round 11
// baseline (speedup 1.0000x reference)
#include <cuda_runtime.h>
#include <cuda_bf16.h>
#include <math_constants.h>

// Problem constants (fixed by setup_inputs)
#define NPTS  16384
#define BATCH 8
#define M     2048
#define CH    128

#define CAP       3072               // per-batch bucket capacity (mean 2048, sd ~42)
#define CHUNK_PTS 16                 // points per block (8 warps x 2 points)
#define NCHUNKS   (CAP / CHUNK_PTS)  // 192
#define FULL 0xffffffffu

typedef unsigned long long ull;

// Device scratch (no allocs allowed)
__device__ float  g_featsT[BATCH * M * CH];   // (B, m, C)
__device__ float4 g_known4[BATCH * M];        // coords padded to float4
__device__ int    g_bucket[BATCH * CAP];      // point ids grouped by batch
__device__ int    g_cnt[BATCH];               // per-batch counts

// ---------------------------------------------------------------------------
// Fused: feats transpose (B,C,m)->(B,m,C), TWO 32x32 XOR-swizzled tiles per
// block (64-wide m tile, MLP=2)                          [z = 0..7]
//      + coord float4 pack / counter zero                [z = 8]
// ---------------------------------------------------------------------------
__global__ void __launch_bounds__(256)
transpose_prep_kernel(const float* __restrict__ feats,
                      const float* __restrict__ known)
{
    const int t = threadIdx.x;
    if (blockIdx.z < BATCH) {
        // element (c,j) of each tile at tile[c*8 + ((j>>2) ^ ((c>>2)&7))].comp(j&3)
        __shared__ float4 tileA[32 * 8];
        __shared__ float4 tileB[32 * 8];
        const int b  = blockIdx.z;
        const int j0 = blockIdx.x * 64;       // m tile (two 32-wide halves)
        const int c0 = blockIdx.y * 32;       // channel tile

        {   // load: thread t -> channel c = t>>3, float4-chunk m4 = t&7
            const int c  = t >> 3;
            const int m4 = t & 7;
            const float* rowp = &feats[((size_t)(b * CH + c0 + c)) * M + j0];
            const float4 vA = *(const float4*)&rowp[m4 * 4];
            const float4 vB = *(const float4*)&rowp[32 + m4 * 4];
            const int sw = c * 8 + (m4 ^ ((c >> 2) & 7));
            tileA[sw] = vA;
            tileB[sw] = vB;
        }
        __syncthreads();
        {   // store: thread t -> m row j = t>>3, channel-chunk q = t&7
            const int j = t >> 3;
            const int q = t & 7;
            const int col4 = j >> 2;
            const int comp = j & 3;
            const float* tfA = (const float*)tileA;
            const float* tfB = (const float*)tileB;
            float vA[4], vB[4];
            #pragma unroll
            for (int i = 0; i < 4; i++) {
                const int c = 4 * q + i;
                const int off = c * 32 + ((col4 ^ ((c >> 2) & 7)) * 4) + comp;
                vA[i] = tfA[off];
                vB[i] = tfB[off];
            }
            *(float4*)&g_featsT[((size_t)(b * M + j0 + j)) * CH + c0 + 4 * q] =
                make_float4(vA[0], vA[1], vA[2], vA[3]);
            *(float4*)&g_featsT[((size_t)(b * M + j0 + 32 + j)) * CH + c0 + 4 * q] =
                make_float4(vB[0], vB[1], vB[2], vB[3]);
        }
    } else {
        const int i = (blockIdx.x * gridDim.y + blockIdx.y) * 256 + t;  // 0..32767
        if (i < BATCH) g_cnt[i] = 0;
        if (i < BATCH * M) {
            const float x = known[3 * i + 0];
            const float y = known[3 * i + 1];
            const float z = known[3 * i + 2];
            g_known4[i] = make_float4(x, y, z, 0.0f);
        }
    }
}

// ---------------------------------------------------------------------------
// Bucket points by batch (order nondeterministic; output invariant to it).
// ---------------------------------------------------------------------------
__global__ void bucket_kernel(const int* __restrict__ batch_inds)
{
    __shared__ int hist[BATCH];
    __shared__ int base[BATCH];
    __shared__ int loc[BATCH];
    const int t = threadIdx.x;
    if (t < BATCH) { hist[t] = 0; loc[t] = 0; }
    __syncthreads();

    const int p = blockIdx.x * blockDim.x + t;
    const int b = batch_inds[p];
    atomicAdd(&hist[b], 1);
    __syncthreads();

    if (t < BATCH) base[t] = atomicAdd(&g_cnt[t], hist[t]);
    __syncthreads();

    const int r   = atomicAdd(&loc[b], 1);
    const int pos = base[b] + r;
    if (pos < CAP) g_bucket[b * CAP + pos] = p;
}

// ---------------------------------------------------------------------------
// Fold every PASSING candidate (ballot mask) into the warp-replicated sorted
// top-3. Keys (d_bits << 32 | idx): uint order of non-negative floats is
// monotone; ties -> lower index (jax top_k semantics). Exact sorted-insert is
// order-independent over the offered set, and every true top-3 member always
// passes the (conservative) threshold test, so the result is exact.
// mask/key are warp-uniform -> uniform branches, no REDUX.
// ---------------------------------------------------------------------------
__device__ __forceinline__ void insert_passing(unsigned mask, float d, int base,
                                               ull& k0, ull& k1, ull& k2)
{
    while (mask) {
        const int src = __ffs(mask) - 1;
        mask &= mask - 1;
        const float ds = __shfl_sync(FULL, d, src);
        const ull key = ((ull)__float_as_uint(ds) << 32) | (unsigned)(base + src);
        if (key < k2) {
            const bool b0 = key < k0, b1 = key < k1;
            k2 = b1 ? k1 : key;
            k1 = b0 ? k0 : (b1 ? key : k1);
            k0 = b0 ? key : k0;
        }
    }
}

// Weights + feature gather + output write for one finished point.
__device__ __forceinline__ void write_point(int pid, int b, ull k0, ull k1, ull k2,
                                            int lane, float* __restrict__ out)
{
    const float d0 = __uint_as_float((unsigned)(k0 >> 32));
    const float d1 = __uint_as_float((unsigned)(k1 >> 32));
    const float d2 = __uint_as_float((unsigned)(k2 >> 32));
    float w0 = 1.0f / (sqrtf(d0) + 1e-8f);
    float w1 = 1.0f / (sqrtf(d1) + 1e-8f);
    float w2 = 1.0f / (sqrtf(d2) + 1e-8f);
    const float inv = 1.0f / (w0 + w1 + w2);
    w0 *= inv; w1 *= inv; w2 *= inv;

    const int i0 = (int)(unsigned)k0;
    const int i1 = (int)(unsigned)k1;
    const int i2 = (int)(unsigned)k2;

    const float4 a0 = ((const float4*)(g_featsT + ((size_t)(b * M + i0)) * CH))[lane];
    const float4 a1 = ((const float4*)(g_featsT + ((size_t)(b * M + i1)) * CH))[lane];
    const float4 a2 = ((const float4*)(g_featsT + ((size_t)(b * M + i2)) * CH))[lane];
    float4 o;
    o.x = fmaf(w0, a0.x, fmaf(w1, a1.x, w2 * a2.x));
    o.y = fmaf(w0, a0.y, fmaf(w1, a1.y, w2 * a2.y));
    o.z = fmaf(w0, a0.z, fmaf(w1, a1.z, w2 * a2.z));
    o.w = fmaf(w0, a0.w, fmaf(w1, a1.w, w2 * a2.w));
    ((float4*)out)[(size_t)pid * (CH / 4) + lane] = o;
}

// ---------------------------------------------------------------------------
// Main: block = (chunk of 16 points, batch). One batch's 2048 coords (float4)
// in 32KB smem. Each warp: 2 same-batch points, 64-candidate vote window.
// Fast path: 2 LDS.128 + 4 exact distances + 4 threshold tests + ONE vote.
// Trigger path: ballot per slice, then shfl-broadcast insert of each passing
// candidate (exact keys, exact tie-break).
// ---------------------------------------------------------------------------
__global__ void __launch_bounds__(256)
knn_main_kernel(const float* __restrict__ unknown, float* __restrict__ out)
{
    __shared__ float4 sc[M];                      // 32 KB
    const int b     = blockIdx.y;
    const int cnt   = g_cnt[b];
    const int start = blockIdx.x * CHUNK_PTS;
    if (start >= cnt) return;                     // uniform exit, pre-sync

    const int t    = threadIdx.x;
    const int lane = t & 31;
    const int w    = t >> 5;

    // Issue point loads first so their latency overlaps the smem fill.
    int   pidA = -1, pidB = -1;
    float uxA = 0.f, uyA = 0.f, uzA = 0.f;
    float uxB = 0.f, uyB = 0.f, uzB = 0.f;
    float t2A = -CUDART_INF_F, t2B = -CUDART_INF_F;   // inactive -> never passes

    const int ibA = start + w * 2;
    const int ibB = ibA + 1;
    if (ibA < cnt) {
        pidA = g_bucket[b * CAP + ibA];
        uxA = unknown[pidA * 3 + 0];
        uyA = unknown[pidA * 3 + 1];
        uzA = unknown[pidA * 3 + 2];
        t2A = CUDART_INF_F;
    }
    if (ibB < cnt) {
        pidB = g_bucket[b * CAP + ibB];
        uxB = unknown[pidB * 3 + 0];
        uyB = unknown[pidB * 3 + 1];
        uzB = unknown[pidB * 3 + 2];
        t2B = CUDART_INF_F;
    }

    {
        const float4* __restrict__ src4 = g_known4 + b * M;
        #pragma unroll
        for (int i = 0; i < M / 256; i++) sc[t + 256 * i] = src4[t + 256 * i];
    }
    __syncthreads();

    ull k0A = ~0ull, k1A = ~0ull, k2A = ~0ull;
    ull k0B = ~0ull, k1B = ~0ull, k2B = ~0ull;

    #pragma unroll 2
    for (int it = 0; it < M / 64; it++) {
        const int base = it * 64;
        const float4 c1 = sc[base + lane];        // idx base+lane
        const float4 c2 = sc[base + 32 + lane];   // idx base+32+lane

        const float dxA1 = c1.x - uxA, dyA1 = c1.y - uyA, dzA1 = c1.z - uzA;
        const float dA1  = fmaf(dxA1, dxA1, fmaf(dyA1, dyA1, dzA1 * dzA1));
        const float dxA2 = c2.x - uxA, dyA2 = c2.y - uyA, dzA2 = c2.z - uzA;
        const float dA2  = fmaf(dxA2, dxA2, fmaf(dyA2, dyA2, dzA2 * dzA2));
        const float dxB1 = c1.x - uxB, dyB1 = c1.y - uyB, dzB1 = c1.z - uzB;
        const float dB1  = fmaf(dxB1, dxB1, fmaf(dyB1, dyB1, dzB1 * dzB1));
        const float dxB2 = c2.x - uxB, dyB2 = c2.y - uyB, dzB2 = c2.z - uzB;
        const float dB2  = fmaf(dxB2, dxB2, fmaf(dyB2, dyB2, dzB2 * dzB2));

        const bool pA1 = dA1 <= t2A, pA2 = dA2 <= t2A;
        const bool pB1 = dB1 <= t2B, pB2 = dB2 <= t2B;

        if (__any_sync(FULL, (pA1 | pA2) | (pB1 | pB2))) {
            const unsigned mA1 = __ballot_sync(FULL, pA1);
            const unsigned mA2 = __ballot_sync(FULL, pA2);
            if (mA1 | mA2) {
                insert_passing(mA1, dA1, base,      k0A, k1A, k2A);
                insert_passing(mA2, dA2, base + 32, k0A, k1A, k2A);
                t2A = __uint_as_float((unsigned)(k2A >> 32));
            }
            const unsigned mB1 = __ballot_sync(FULL, pB1);
            const unsigned mB2 = __ballot_sync(FULL, pB2);
            if (mB1 | mB2) {
                insert_passing(mB1, dB1, base,      k0B, k1B, k2B);
                insert_passing(mB2, dB2, base + 32, k0B, k1B, k2B);
                t2B = __uint_as_float((unsigned)(k2B >> 32));
            }
        }
    }

    if (pidA >= 0) write_point(pidA, b, k0A, k1A, k2A, lane, out);
    if (pidB >= 0) write_point(pidB, b, k0B, k1B, k2B, lane, out);
}

// ---------------------------------------------------------------------------
extern "C" void kernel_launch(void* const* d_in, const int* in_sizes, int n_in,
                              void* d_out, int out_size)
{
    const float* unknown     = (const float*)d_in[0];
    const float* known       = (const float*)d_in[1];
    const int*   batch_inds  = (const int*)d_in[2];
    const float* known_feats = (const float*)d_in[3];
    float* out = (float*)d_out;

    transpose_prep_kernel<<<dim3(M / 64, CH / 32, BATCH + 1), 256>>>(known_feats, known);
    bucket_kernel<<<NPTS / 256, 256>>>(batch_inds);
    knn_main_kernel<<<dim3(NCHUNKS, BATCH), 256>>>(unknown, out);
}

// round 12
// speedup vs baseline: 1.3932x; 1.3932x over previous
#include <cuda_runtime.h>
#include <cuda_bf16.h>
#include <math_constants.h>

// Problem constants (fixed by setup_inputs)
#define NPTS  16384
#define BATCH 8
#define M     2048
#define CH    128

#define CAP       3072               // per-batch bucket capacity (mean 2048, sd ~42)
#define CHUNK_PTS 16                 // points per block (8 warps x 2 points)
#define NCHUNKS   (CAP / CHUNK_PTS)  // 192
#define FULL 0xffffffffu

typedef unsigned long long ull;

// Device scratch (no allocs allowed)
__device__ float  g_featsT[BATCH * M * CH];   // (B, m, C)
__device__ float4 g_known4[BATCH * M];        // coords padded to float4
__device__ int    g_bucket[BATCH * CAP];      // point ids grouped by batch
__device__ int    g_cnt[BATCH];               // per-batch counts

// ---------------------------------------------------------------------------
// Fused: feats transpose (B,C,m)->(B,m,C), TWO 32x32 XOR-swizzled tiles per
// block (64-wide m tile, MLP=2)                          [z = 0..7]
//      + coord float4 pack / counter zero                [z = 8]
// ---------------------------------------------------------------------------
__global__ void __launch_bounds__(256)
transpose_prep_kernel(const float* __restrict__ feats,
                      const float* __restrict__ known)
{
    const int t = threadIdx.x;
    if (blockIdx.z < BATCH) {
        // element (c,j) of each tile at tile[c*8 + ((j>>2) ^ ((c>>2)&7))].comp(j&3)
        __shared__ float4 tileA[32 * 8];
        __shared__ float4 tileB[32 * 8];
        const int b  = blockIdx.z;
        const int j0 = blockIdx.x * 64;       // m tile (two 32-wide halves)
        const int c0 = blockIdx.y * 32;       // channel tile

        {   // load: thread t -> channel c = t>>3, float4-chunk m4 = t&7
            const int c  = t >> 3;
            const int m4 = t & 7;
            const float* rowp = &feats[((size_t)(b * CH + c0 + c)) * M + j0];
            const float4 vA = *(const float4*)&rowp[m4 * 4];
            const float4 vB = *(const float4*)&rowp[32 + m4 * 4];
            const int sw = c * 8 + (m4 ^ ((c >> 2) & 7));
            tileA[sw] = vA;
            tileB[sw] = vB;
        }
        __syncthreads();
        {   // store: thread t -> m row j = t>>3, channel-chunk q = t&7
            const int j = t >> 3;
            const int q = t & 7;
            const int col4 = j >> 2;
            const int comp = j & 3;
            const float* tfA = (const float*)tileA;
            const float* tfB = (const float*)tileB;
            float vA[4], vB[4];
            #pragma unroll
            for (int i = 0; i < 4; i++) {
                const int c = 4 * q + i;
                const int off = c * 32 + ((col4 ^ ((c >> 2) & 7)) * 4) + comp;
                vA[i] = tfA[off];
                vB[i] = tfB[off];
            }
            *(float4*)&g_featsT[((size_t)(b * M + j0 + j)) * CH + c0 + 4 * q] =
                make_float4(vA[0], vA[1], vA[2], vA[3]);
            *(float4*)&g_featsT[((size_t)(b * M + j0 + 32 + j)) * CH + c0 + 4 * q] =
                make_float4(vB[0], vB[1], vB[2], vB[3]);
        }
    } else {
        const int i = (blockIdx.x * gridDim.y + blockIdx.y) * 256 + t;  // 0..32767
        if (i < BATCH) g_cnt[i] = 0;
        if (i < BATCH * M) {
            const float x = known[3 * i + 0];
            const float y = known[3 * i + 1];
            const float z = known[3 * i + 2];
            g_known4[i] = make_float4(x, y, z, 0.0f);
        }
    }
}

// ---------------------------------------------------------------------------
// Bucket points by batch (order nondeterministic; output invariant to it).
// ---------------------------------------------------------------------------
__global__ void bucket_kernel(const int* __restrict__ batch_inds)
{
    __shared__ int hist[BATCH];
    __shared__ int base[BATCH];
    __shared__ int loc[BATCH];
    const int t = threadIdx.x;
    if (t < BATCH) { hist[t] = 0; loc[t] = 0; }
    __syncthreads();

    const int p = blockIdx.x * blockDim.x + t;
    const int b = batch_inds[p];
    atomicAdd(&hist[b], 1);
    __syncthreads();

    if (t < BATCH) base[t] = atomicAdd(&g_cnt[t], hist[t]);
    __syncthreads();

    const int r   = atomicAdd(&loc[b], 1);
    const int pos = base[b] + r;
    if (pos < CAP) g_bucket[b * CAP + pos] = p;
}

// ---------------------------------------------------------------------------
// Guarded sorted insert of one warp-uniform key into replicated top-3.
// ---------------------------------------------------------------------------
__device__ __forceinline__ void sorted_insert(ull key, ull& k0, ull& k1, ull& k2)
{
    if (key < k2) {
        const bool b0 = key < k0, b1 = key < k1;
        k2 = b1 ? k1 : key;
        k1 = b0 ? k0 : (b1 ? key : k1);
        k0 = b0 ? key : k0;
    }
}

// ---------------------------------------------------------------------------
// Hybrid slice merge. mask = ballot of passing lanes (warp-uniform).
// n==1 (common, post-seed): one shfl broadcast + guarded insert, no loop.
// n>1  (seed window / rare): REDUX-min loop, extracts ascending, EARLY-BREAKS
// once nothing can beat k2 (<=4 iterations even when all 32 pass).
// Keys (d_bits << 32 | idx): uint order of non-negative floats is monotone;
// ties -> lower index (jax top_k). Order-independent over the offered set.
// ---------------------------------------------------------------------------
__device__ __forceinline__ void merge_slice(unsigned mask, float d, int base, int lane,
                                            ull& k0, ull& k1, ull& k2)
{
    if (mask == 0) return;
    if ((mask & (mask - 1)) == 0) {               // exactly one passing lane
        const int src = __ffs(mask) - 1;
        const float ds = __shfl_sync(FULL, d, src);
        const ull key = ((ull)__float_as_uint(ds) << 32) | (unsigned)(base + src);
        sorted_insert(key, k0, k1, k2);
        return;
    }
    unsigned cur = ((mask >> lane) & 1u) ? __float_as_uint(d) : 0xFFFFFFFFu;
    while (true) {
        const unsigned mind   = __reduce_min_sync(FULL, cur);
        const unsigned owners = __ballot_sync(FULL, cur == mind);
        const int      src    = __ffs(owners) - 1;      // lowest lane = lowest idx
        const ull      mkey   = ((ull)mind << 32) | (unsigned)(base + src);
        if (mkey >= k2) break;
        sorted_insert(mkey, k0, k1, k2);
        if (lane == src) cur = 0xFFFFFFFFu;             // consume winner
        if (!__any_sync(FULL, cur <= (unsigned)(k2 >> 32))) break;
    }
}

// Weights + feature gather + output write for one finished point.
__device__ __forceinline__ void write_point(int pid, int b, ull k0, ull k1, ull k2,
                                            int lane, float* __restrict__ out)
{
    const float d0 = __uint_as_float((unsigned)(k0 >> 32));
    const float d1 = __uint_as_float((unsigned)(k1 >> 32));
    const float d2 = __uint_as_float((unsigned)(k2 >> 32));
    float w0 = 1.0f / (sqrtf(d0) + 1e-8f);
    float w1 = 1.0f / (sqrtf(d1) + 1e-8f);
    float w2 = 1.0f / (sqrtf(d2) + 1e-8f);
    const float inv = 1.0f / (w0 + w1 + w2);
    w0 *= inv; w1 *= inv; w2 *= inv;

    const int i0 = (int)(unsigned)k0;
    const int i1 = (int)(unsigned)k1;
    const int i2 = (int)(unsigned)k2;

    const float4 a0 = ((const float4*)(g_featsT + ((size_t)(b * M + i0)) * CH))[lane];
    const float4 a1 = ((const float4*)(g_featsT + ((size_t)(b * M + i1)) * CH))[lane];
    const float4 a2 = ((const float4*)(g_featsT + ((size_t)(b * M + i2)) * CH))[lane];
    float4 o;
    o.x = fmaf(w0, a0.x, fmaf(w1, a1.x, w2 * a2.x));
    o.y = fmaf(w0, a0.y, fmaf(w1, a1.y, w2 * a2.y));
    o.z = fmaf(w0, a0.z, fmaf(w1, a1.z, w2 * a2.z));
    o.w = fmaf(w0, a0.w, fmaf(w1, a1.w, w2 * a2.w));
    ((float4*)out)[(size_t)pid * (CH / 4) + lane] = o;
}

// ---------------------------------------------------------------------------
// Main: block = (chunk of 16 points, batch). One batch's 2048 coords (float4)
// in 32KB smem. Each warp: 2 same-batch points, 64-candidate vote window.
// Fast path: 2 LDS.128 + 4 exact distances + 4 threshold tests + ONE vote.
// Trigger path: per-slice ballot -> hybrid merge (single-shfl or REDUX loop).
// ---------------------------------------------------------------------------
__global__ void __launch_bounds__(256)
knn_main_kernel(const float* __restrict__ unknown, float* __restrict__ out)
{
    __shared__ float4 sc[M];                      // 32 KB
    const int b     = blockIdx.y;
    const int cnt   = g_cnt[b];
    const int start = blockIdx.x * CHUNK_PTS;
    if (start >= cnt) return;                     // uniform exit, pre-sync

    const int t    = threadIdx.x;
    const int lane = t & 31;
    const int w    = t >> 5;

    // Issue point loads first so their latency overlaps the smem fill.
    int   pidA = -1, pidB = -1;
    float uxA = 0.f, uyA = 0.f, uzA = 0.f;
    float uxB = 0.f, uyB = 0.f, uzB = 0.f;
    float t2A = -CUDART_INF_F, t2B = -CUDART_INF_F;   // inactive -> never passes

    const int ibA = start + w * 2;
    const int ibB = ibA + 1;
    if (ibA < cnt) {
        pidA = g_bucket[b * CAP + ibA];
        uxA = unknown[pidA * 3 + 0];
        uyA = unknown[pidA * 3 + 1];
        uzA = unknown[pidA * 3 + 2];
        t2A = CUDART_INF_F;
    }
    if (ibB < cnt) {
        pidB = g_bucket[b * CAP + ibB];
        uxB = unknown[pidB * 3 + 0];
        uyB = unknown[pidB * 3 + 1];
        uzB = unknown[pidB * 3 + 2];
        t2B = CUDART_INF_F;
    }

    {
        const float4* __restrict__ src4 = g_known4 + b * M;
        #pragma unroll
        for (int i = 0; i < M / 256; i++) sc[t + 256 * i] = src4[t + 256 * i];
    }
    __syncthreads();

    ull k0A = ~0ull, k1A = ~0ull, k2A = ~0ull;
    ull k0B = ~0ull, k1B = ~0ull, k2B = ~0ull;

    #pragma unroll 2
    for (int it = 0; it < M / 64; it++) {
        const int base = it * 64;
        const float4 c1 = sc[base + lane];        // idx base+lane
        const float4 c2 = sc[base + 32 + lane];   // idx base+32+lane

        const float dxA1 = c1.x - uxA, dyA1 = c1.y - uyA, dzA1 = c1.z - uzA;
        const float dA1  = fmaf(dxA1, dxA1, fmaf(dyA1, dyA1, dzA1 * dzA1));
        const float dxA2 = c2.x - uxA, dyA2 = c2.y - uyA, dzA2 = c2.z - uzA;
        const float dA2  = fmaf(dxA2, dxA2, fmaf(dyA2, dyA2, dzA2 * dzA2));
        const float dxB1 = c1.x - uxB, dyB1 = c1.y - uyB, dzB1 = c1.z - uzB;
        const float dB1  = fmaf(dxB1, dxB1, fmaf(dyB1, dyB1, dzB1 * dzB1));
        const float dxB2 = c2.x - uxB, dyB2 = c2.y - uyB, dzB2 = c2.z - uzB;
        const float dB2  = fmaf(dxB2, dxB2, fmaf(dyB2, dyB2, dzB2 * dzB2));

        const bool pA1 = dA1 <= t2A, pA2 = dA2 <= t2A;
        const bool pB1 = dB1 <= t2B, pB2 = dB2 <= t2B;

        if (__any_sync(FULL, (pA1 | pA2) | (pB1 | pB2))) {
            const unsigned mA1 = __ballot_sync(FULL, pA1);
            const unsigned mA2 = __ballot_sync(FULL, pA2);
            if (mA1 | mA2) {
                merge_slice(mA1, dA1, base,      lane, k0A, k1A, k2A);
                merge_slice(mA2, dA2, base + 32, lane, k0A, k1A, k2A);
                t2A = __uint_as_float((unsigned)(k2A >> 32));
            }
            const unsigned mB1 = __ballot_sync(FULL, pB1);
            const unsigned mB2 = __ballot_sync(FULL, pB2);
            if (mB1 | mB2) {
                merge_slice(mB1, dB1, base,      lane, k0B, k1B, k2B);
                merge_slice(mB2, dB2, base + 32, lane, k0B, k1B, k2B);
                t2B = __uint_as_float((unsigned)(k2B >> 32));
            }
        }
    }

    if (pidA >= 0) write_point(pidA, b, k0A, k1A, k2A, lane, out);
    if (pidB >= 0) write_point(pidB, b, k0B, k1B, k2B, lane, out);
}

// ---------------------------------------------------------------------------
extern "C" void kernel_launch(void* const* d_in, const int* in_sizes, int n_in,
                              void* d_out, int out_size)
{
    const float* unknown     = (const float*)d_in[0];
    const float* known       = (const float*)d_in[1];
    const int*   batch_inds  = (const int*)d_in[2];
    const float* known_feats = (const float*)d_in[3];
    float* out = (float*)d_out;

    transpose_prep_kernel<<<dim3(M / 64, CH / 32, BATCH + 1), 256>>>(known_feats, known);
    bucket_kernel<<<NPTS / 256, 256>>>(batch_inds);
    knn_main_kernel<<<dim3(NCHUNKS, BATCH), 256>>>(unknown, out);
}

// round 13
// speedup vs baseline: 1.5171x; 1.0889x over previous
#include <cuda_runtime.h>
#include <cuda_bf16.h>
#include <math_constants.h>

// Problem constants (fixed by setup_inputs)
#define NPTS  16384
#define BATCH 8
#define M     2048
#define CH    128

#define CAP       3072               // per-batch bucket capacity (mean 2048, sd ~42)
#define CHUNK_PTS 16                 // points per block (8 warps x 2 points)
#define NCHUNKS   (CAP / CHUNK_PTS)  // 192
#define FULL 0xffffffffu

typedef unsigned long long ull;

// Device scratch (no allocs allowed)
__device__ float g_featsT[BATCH * M * CH];   // (B, m, C)
__device__ float g_ksoa[BATCH * 3 * M];      // coords SoA: [b][xyz][m]
__device__ int   g_bucket[BATCH * CAP];      // point ids grouped by batch
__device__ int   g_cnt[BATCH];               // per-batch counts

// ---------------------------------------------------------------------------
// f32x2 packed helpers. Per-lane results are bit-identical to the scalar
// FADD/FFMA chain (IEEE rn each half, same association).
// ---------------------------------------------------------------------------
__device__ __forceinline__ ull pack2(float lo, float hi) {
    ull r; asm("mov.b64 %0, {%1, %2};" : "=l"(r) : "f"(lo), "f"(hi)); return r;
}
__device__ __forceinline__ void unpack2(ull v, float& lo, float& hi) {
    asm("mov.b64 {%0, %1}, %2;" : "=f"(lo), "=f"(hi) : "l"(v));   // reg-pair alias, free
}
__device__ __forceinline__ ull add2(ull a, ull b) {
    ull r; asm("add.rn.f32x2 %0, %1, %2;" : "=l"(r) : "l"(a), "l"(b)); return r;
}
__device__ __forceinline__ ull mul2(ull a, ull b) {
    ull r; asm("mul.rn.f32x2 %0, %1, %2;" : "=l"(r) : "l"(a), "l"(b)); return r;
}
__device__ __forceinline__ ull fma2(ull a, ull b, ull c) {
    ull r; asm("fma.rn.f32x2 %0, %1, %2, %3;" : "=l"(r) : "l"(a), "l"(b), "l"(c)); return r;
}

// ---------------------------------------------------------------------------
// Fused: feats transpose (B,C,m)->(B,m,C), TWO 32x32 XOR-swizzled tiles per
// block (64-wide m tile, MLP=2)                          [z = 0..7]
//      + coord SoA split / counter zero                  [z = 8]
// ---------------------------------------------------------------------------
__global__ void __launch_bounds__(256)
transpose_prep_kernel(const float* __restrict__ feats,
                      const float* __restrict__ known)
{
    const int t = threadIdx.x;
    if (blockIdx.z < BATCH) {
        // element (c,j) of each tile at tile[c*8 + ((j>>2) ^ ((c>>2)&7))].comp(j&3)
        __shared__ float4 tileA[32 * 8];
        __shared__ float4 tileB[32 * 8];
        const int b  = blockIdx.z;
        const int j0 = blockIdx.x * 64;       // m tile (two 32-wide halves)
        const int c0 = blockIdx.y * 32;       // channel tile

        {   // load: thread t -> channel c = t>>3, float4-chunk m4 = t&7
            const int c  = t >> 3;
            const int m4 = t & 7;
            const float* rowp = &feats[((size_t)(b * CH + c0 + c)) * M + j0];
            const float4 vA = *(const float4*)&rowp[m4 * 4];
            const float4 vB = *(const float4*)&rowp[32 + m4 * 4];
            const int sw = c * 8 + (m4 ^ ((c >> 2) & 7));
            tileA[sw] = vA;
            tileB[sw] = vB;
        }
        __syncthreads();
        {   // store: thread t -> m row j = t>>3, channel-chunk q = t&7
            const int j = t >> 3;
            const int q = t & 7;
            const int col4 = j >> 2;
            const int comp = j & 3;
            const float* tfA = (const float*)tileA;
            const float* tfB = (const float*)tileB;
            float vA[4], vB[4];
            #pragma unroll
            for (int i = 0; i < 4; i++) {
                const int c = 4 * q + i;
                const int off = c * 32 + ((col4 ^ ((c >> 2) & 7)) * 4) + comp;
                vA[i] = tfA[off];
                vB[i] = tfB[off];
            }
            *(float4*)&g_featsT[((size_t)(b * M + j0 + j)) * CH + c0 + 4 * q] =
                make_float4(vA[0], vA[1], vA[2], vA[3]);
            *(float4*)&g_featsT[((size_t)(b * M + j0 + 32 + j)) * CH + c0 + 4 * q] =
                make_float4(vB[0], vB[1], vB[2], vB[3]);
        }
    } else {
        const int i = (blockIdx.x * gridDim.y + blockIdx.y) * 256 + t;  // 0..32767
        if (i < BATCH) g_cnt[i] = 0;
        if (i < BATCH * M) {
            const int b = i / M, j = i - b * M;
            g_ksoa[(b * 3 + 0) * M + j] = known[3 * i + 0];
            g_ksoa[(b * 3 + 1) * M + j] = known[3 * i + 1];
            g_ksoa[(b * 3 + 2) * M + j] = known[3 * i + 2];
        }
    }
}

// ---------------------------------------------------------------------------
// Bucket points by batch (order nondeterministic; output invariant to it).
// ---------------------------------------------------------------------------
__global__ void bucket_kernel(const int* __restrict__ batch_inds)
{
    __shared__ int hist[BATCH];
    __shared__ int base[BATCH];
    __shared__ int loc[BATCH];
    const int t = threadIdx.x;
    if (t < BATCH) { hist[t] = 0; loc[t] = 0; }
    __syncthreads();

    const int p = blockIdx.x * blockDim.x + t;
    const int b = batch_inds[p];
    atomicAdd(&hist[b], 1);
    __syncthreads();

    if (t < BATCH) base[t] = atomicAdd(&g_cnt[t], hist[t]);
    __syncthreads();

    const int r   = atomicAdd(&loc[b], 1);
    const int pos = base[b] + r;
    if (pos < CAP) g_bucket[b * CAP + pos] = p;
}

// ---------------------------------------------------------------------------
// Warp-collective EXACT top-3 update (R9-proven REDUX loop, early-breaking).
// Candidate index of lane src is off + 2*src (monotone in src -> lowest
// owner lane = lowest index). Keys (d_bits << 32 | idx): uint order of
// non-negative floats is monotone; ties -> lower index (jax top_k).
// ---------------------------------------------------------------------------
__device__ __forceinline__ void topk_update(bool pass, float d, int off, int lane,
                                            ull& k0, ull& k1, ull& k2)
{
    unsigned cur = pass ? __float_as_uint(d) : 0xFFFFFFFFu;
    while (true) {
        const unsigned mind   = __reduce_min_sync(FULL, cur);
        const unsigned owners = __ballot_sync(FULL, cur == mind);
        const int      src    = __ffs(owners) - 1;      // lowest lane = lowest idx
        const ull      mkey   = ((ull)mind << 32) | (unsigned)(off + (src << 1));
        if (mkey >= k2) break;
        const bool b0 = mkey < k0, b1 = mkey < k1;
        k2 = b1 ? k1 : mkey;
        k1 = b0 ? k0 : (b1 ? mkey : k1);
        k0 = b0 ? mkey : k0;
        if (lane == src) cur = 0xFFFFFFFFu;             // consume winner
        if (!__any_sync(FULL, cur <= (unsigned)(k2 >> 32))) break;  // cheap pre-break
    }
}

// Weights + feature gather + output write for one finished point.
__device__ __forceinline__ void write_point(int pid, int b, ull k0, ull k1, ull k2,
                                            int lane, float* __restrict__ out)
{
    const float d0 = __uint_as_float((unsigned)(k0 >> 32));
    const float d1 = __uint_as_float((unsigned)(k1 >> 32));
    const float d2 = __uint_as_float((unsigned)(k2 >> 32));
    float w0 = 1.0f / (sqrtf(d0) + 1e-8f);
    float w1 = 1.0f / (sqrtf(d1) + 1e-8f);
    float w2 = 1.0f / (sqrtf(d2) + 1e-8f);
    const float inv = 1.0f / (w0 + w1 + w2);
    w0 *= inv; w1 *= inv; w2 *= inv;

    const int i0 = (int)(unsigned)k0;
    const int i1 = (int)(unsigned)k1;
    const int i2 = (int)(unsigned)k2;

    const float4 a0 = ((const float4*)(g_featsT + ((size_t)(b * M + i0)) * CH))[lane];
    const float4 a1 = ((const float4*)(g_featsT + ((size_t)(b * M + i1)) * CH))[lane];
    const float4 a2 = ((const float4*)(g_featsT + ((size_t)(b * M + i2)) * CH))[lane];
    float4 o;
    o.x = fmaf(w0, a0.x, fmaf(w1, a1.x, w2 * a2.x));
    o.y = fmaf(w0, a0.y, fmaf(w1, a1.y, w2 * a2.y));
    o.z = fmaf(w0, a0.z, fmaf(w1, a1.z, w2 * a2.z));
    o.w = fmaf(w0, a0.w, fmaf(w1, a1.w, w2 * a2.w));
    ((float4*)out)[(size_t)pid * (CH / 4) + lane] = o;
}

// ---------------------------------------------------------------------------
// Main: block = (chunk of 16 points, batch). One batch's 2048 coords in SoA
// smem (24KB). Each warp: 2 same-batch points; each lane: one candidate PAIR
// per 64-candidate window via 3 LDS.64 + packed f32x2 distance math
// (bit-identical rounding to the scalar chain). One vote per window; exact
// REDUX top-3 merge on triggering windows only.
// ---------------------------------------------------------------------------
__global__ void __launch_bounds__(256)
knn_main_kernel(const float* __restrict__ unknown, float* __restrict__ out)
{
    __shared__ __align__(16) float sco[3 * M];    // sx | sy | sz, 24 KB
    const int b     = blockIdx.y;
    const int cnt   = g_cnt[b];
    const int start = blockIdx.x * CHUNK_PTS;
    if (start >= cnt) return;                     // uniform exit, pre-sync

    const int t    = threadIdx.x;
    const int lane = t & 31;
    const int w    = t >> 5;

    // Point loads first so their latency overlaps the smem fill.
    int pidA = -1, pidB = -1;
    ull nxA = 0, nyA = 0, nzA = 0;
    ull nxB = 0, nyB = 0, nzB = 0;
    float t2A = -CUDART_INF_F, t2B = -CUDART_INF_F;   // inactive -> never passes

    const int ibA = start + w * 2;
    const int ibB = ibA + 1;
    if (ibA < cnt) {
        pidA = g_bucket[b * CAP + ibA];
        const float x = unknown[pidA * 3 + 0];
        const float y = unknown[pidA * 3 + 1];
        const float z = unknown[pidA * 3 + 2];
        nxA = pack2(-x, -x); nyA = pack2(-y, -y); nzA = pack2(-z, -z);
        t2A = CUDART_INF_F;
    }
    if (ibB < cnt) {
        pidB = g_bucket[b * CAP + ibB];
        const float x = unknown[pidB * 3 + 0];
        const float y = unknown[pidB * 3 + 1];
        const float z = unknown[pidB * 3 + 2];
        nxB = pack2(-x, -x); nyB = pack2(-y, -y); nzB = pack2(-z, -z);
        t2B = CUDART_INF_F;
    }

    {
        const float4* __restrict__ src4 = (const float4*)(g_ksoa + b * 3 * M);
        #pragma unroll
        for (int i = 0; i < 3 * M / 4 / 256; i++)
            ((float4*)sco)[t + 256 * i] = src4[t + 256 * i];
    }
    __syncthreads();

    const float* sx = sco;
    const float* sy = sco + M;
    const float* sz = sco + 2 * M;

    ull k0A = ~0ull, k1A = ~0ull, k2A = ~0ull;
    ull k0B = ~0ull, k1B = ~0ull, k2B = ~0ull;

    #pragma unroll 4
    for (int it = 0; it < M / 64; it++) {
        const int cb = it * 64 + 2 * lane;        // lane's candidate pair: cb, cb+1
        const ull cx2 = *(const ull*)&sx[cb];
        const ull cy2 = *(const ull*)&sy[cb];
        const ull cz2 = *(const ull*)&sz[cb];

        // packed distances: per-half identical to fmaf(dx,dx,fmaf(dy,dy,dz*dz))
        const ull dxA = add2(cx2, nxA), dyA = add2(cy2, nyA), dzA = add2(cz2, nzA);
        const ull ddA = fma2(dxA, dxA, fma2(dyA, dyA, mul2(dzA, dzA)));
        const ull dxB = add2(cx2, nxB), dyB = add2(cy2, nyB), dzB = add2(cz2, nzB);
        const ull ddB = fma2(dxB, dxB, fma2(dyB, dyB, mul2(dzB, dzB)));

        float dA1, dA2, dB1, dB2;
        unpack2(ddA, dA1, dA2);                   // free (register-pair halves)
        unpack2(ddB, dB1, dB2);

        const bool pA1 = dA1 <= t2A, pA2 = dA2 <= t2A;
        const bool pB1 = dB1 <= t2B, pB2 = dB2 <= t2B;

        if (__any_sync(FULL, (pA1 | pA2) | (pB1 | pB2))) {
            const int base = it * 64;
            if (__any_sync(FULL, pA1 | pA2)) {
                if (__any_sync(FULL, pA1)) topk_update(pA1, dA1, base,     lane, k0A, k1A, k2A);
                if (__any_sync(FULL, pA2)) topk_update(pA2, dA2, base + 1, lane, k0A, k1A, k2A);
                t2A = __uint_as_float((unsigned)(k2A >> 32));
            }
            if (__any_sync(FULL, pB1 | pB2)) {
                if (__any_sync(FULL, pB1)) topk_update(pB1, dB1, base,     lane, k0B, k1B, k2B);
                if (__any_sync(FULL, pB2)) topk_update(pB2, dB2, base + 1, lane, k0B, k1B, k2B);
                t2B = __uint_as_float((unsigned)(k2B >> 32));
            }
        }
    }

    if (pidA >= 0) write_point(pidA, b, k0A, k1A, k2A, lane, out);
    if (pidB >= 0) write_point(pidB, b, k0B, k1B, k2B, lane, out);
}

// ---------------------------------------------------------------------------
extern "C" void kernel_launch(void* const* d_in, const int* in_sizes, int n_in,
                              void* d_out, int out_size)
{
    const float* unknown     = (const float*)d_in[0];
    const float* known       = (const float*)d_in[1];
    const int*   batch_inds  = (const int*)d_in[2];
    const float* known_feats = (const float*)d_in[3];
    float* out = (float*)d_out;

    transpose_prep_kernel<<<dim3(M / 64, CH / 32, BATCH + 1), 256>>>(known_feats, known);
    bucket_kernel<<<NPTS / 256, 256>>>(batch_inds);
    knn_main_kernel<<<dim3(NCHUNKS, BATCH), 256>>>(unknown, out);
}